// round 13
// baseline (speedup 1.0000x reference)
#include <cuda_runtime.h>
#include <cuda_bf16.h>
#include <cuda_fp16.h>
#include <cstdint>

#define NN 50000
#define EE 400000
#define DD 128
#define HH 2
#define CC 128
#define TE (EE + NN)

// ---------------- static scratch ----------------
__device__ __half g_xn[NN * DD];                 // fp16 relu(layernorm(x))
__device__ __half g_Wt[3 * 256 * 128];           // W^T per block, [n][k] fp16
__device__ uint32_t g_h[2 * 2 * NN * 64];        // bf16x2 msgs: [buf][head][node][64]
__device__ float  g_va[3][4][128];               // W^T @ att vectors (s0,s1,d0,d1)
__device__ float  g_as[NN * HH];                 // alpha_src
__device__ float  g_ad[NN * HH];                 // alpha_dst
__device__ float2 g_w[TE];                       // per-edge softmax weights
__device__ int    g_rowptr[NN + 1];
__device__ int    g_wptr[NN];
__device__ int    g_col[TE];
__device__ int    g_dst[TE];
__device__ int    g_cnt[NN];                     // zero-init; self-resets each launch
__device__ int    g_bsum[64];

__device__ __forceinline__ float wred(float v) {
#pragma unroll
    for (int o = 16; o > 0; o >>= 1) v += __shfl_xor_sync(0xffffffffu, v, o);
    return v;
}

// ---------------- CSR build (multi-block scan) ----------------
__global__ void k_count(const int* __restrict__ ei, int E) {
    int e = blockIdx.x * blockDim.x + threadIdx.x;
    if (e < E) atomicAdd(&g_cnt[ei[E + e]], 1);
}

__global__ void k_scan1(int n) {
    __shared__ int wsum[32];
    int i = blockIdx.x * 1024 + threadIdx.x;
    int v = (i < n) ? (g_cnt[i] + 1) : 0;        // +1 = self-loop
    if (i < n) g_cnt[i] = 0;                     // reset for next graph replay
    int lane = threadIdx.x & 31, w = threadIdx.x >> 5;
    int s = v;
#pragma unroll
    for (int o = 1; o < 32; o <<= 1) {
        int t = __shfl_up_sync(0xffffffffu, s, o);
        if (lane >= o) s += t;
    }
    if (lane == 31) wsum[w] = s;
    __syncthreads();
    if (w == 0) {
        int t = wsum[lane];
#pragma unroll
        for (int o = 1; o < 32; o <<= 1) {
            int u = __shfl_up_sync(0xffffffffu, t, o);
            if (lane >= o) t += u;
        }
        wsum[lane] = t;
    }
    __syncthreads();
    int off  = (w > 0) ? wsum[w - 1] : 0;
    int incl = s + off;
    if (i < n) g_rowptr[i] = incl - v;
    if (threadIdx.x == 1023) g_bsum[blockIdx.x] = incl;
}

__global__ void k_scan3(int n, int tot) {
    __shared__ int pfx[2];
    int base = blockIdx.x * 256;
    if (threadIdx.x < 2) {
        int idx = base + (int)threadIdx.x * 255;
        if (idx >= n) idx = n - 1;
        int chunk = idx >> 10;
        int acc = 0;
        for (int j = 0; j < chunk; j++) acc += g_bsum[j];
        pfx[threadIdx.x] = acc;
    }
    __syncthreads();
    int i = base + threadIdx.x;
    if (i < n) {
        int sel = ((i >> 10) != (base >> 10)) ? 1 : 0;
        int r = g_rowptr[i] + pfx[sel];
        g_rowptr[i] = r;
        g_wptr[i]   = r;
    }
    if (i == 0) g_rowptr[n] = tot;
}

__global__ void k_scatter(const int* __restrict__ ei, int E, int n) {
    int e = blockIdx.x * blockDim.x + threadIdx.x;
    int tot = E + n;
    if (e >= tot) return;
    int s, d;
    if (e < E) { s = ei[e]; d = ei[E + e]; }
    else       { s = e - E; d = s; }
    int p = atomicAdd(&g_wptr[d], 1);
    g_col[p] = s;
    g_dst[p] = d;
}

// ---------------- va = W^T @ att vectors ----------------
__global__ void k_va(const float* __restrict__ W, const float* __restrict__ as_,
                     const float* __restrict__ ad_) {
    int b = blockIdx.x;
    int vec = threadIdx.x >> 7;
    int k   = threadIdx.x & 127;
    int h   = vec & 1;
    const float* av = (vec < 2 ? as_ : ad_) + b * 256 + h * 128;
    const float* wr = W + b * 32768 + k * 256 + h * 128;
    float sum = 0.f;
#pragma unroll 8
    for (int c = 0; c < 128; c++) sum += wr[c] * av[c];
    g_va[b][vec][k] = sum;
}

// ---------------- W transpose + fp16 convert ----------------
__global__ void k_wt(const float* __restrict__ W) {
    int idx = blockIdx.x * 256 + threadIdx.x;
    if (idx >= 3 * 128 * 64) return;
    int b  = idx >> 13;
    int r  = idx & 8191;
    int k  = r >> 6;
    int n4 = r & 63;
    float4 v = *reinterpret_cast<const float4*>(&W[b * 32768 + k * 256 + n4 * 4]);
    __half* dst = &g_Wt[b * 32768];
    dst[(n4 * 4 + 0) * 128 + k] = __float2half_rn(v.x);
    dst[(n4 * 4 + 1) * 128 + k] = __float2half_rn(v.y);
    dst[(n4 * 4 + 2) * 128 + k] = __float2half_rn(v.z);
    dst[(n4 * 4 + 3) * 128 + k] = __float2half_rn(v.w);
}

// ---------------- LayerNorm + ReLU -> fp16 + alphas (block 0) ----------------
__global__ void k_ln(const float* __restrict__ x, const float* __restrict__ gamma,
                     const float* __restrict__ beta, int n) {
    int row = blockIdx.x * 8 + (threadIdx.x >> 5);
    if (row >= n) return;
    int lane = threadIdx.x & 31;
    float4 v = *reinterpret_cast<const float4*>(&x[row * DD + lane * 4]);
    float s = wred(v.x + v.y + v.z + v.w);
    float q = wred(v.x * v.x + v.y * v.y + v.z * v.z + v.w * v.w);
    float mu  = s * (1.0f / DD);
    float var = q * (1.0f / DD) - mu * mu;
    float rs  = rsqrtf(var + 1e-5f);
    float4 g = *reinterpret_cast<const float4*>(&gamma[lane * 4]);
    float4 b = *reinterpret_cast<const float4*>(&beta[lane * 4]);
    float n0 = fmaxf(0.f, (v.x - mu) * rs * g.x + b.x);
    float n1 = fmaxf(0.f, (v.y - mu) * rs * g.y + b.y);
    float n2 = fmaxf(0.f, (v.z - mu) * rs * g.z + b.z);
    float n3 = fmaxf(0.f, (v.w - mu) * rs * g.w + b.w);
    __half2 h0 = __floats2half2_rn(n0, n1);
    __half2 h1 = __floats2half2_rn(n2, n3);
    uint2 u;
    u.x = *reinterpret_cast<uint32_t*>(&h0);
    u.y = *reinterpret_cast<uint32_t*>(&h1);
    *reinterpret_cast<uint2*>(&g_xn[row * DD + lane * 4]) = u;
    float4 vs0 = *reinterpret_cast<const float4*>(&g_va[0][0][lane * 4]);
    float4 vs1 = *reinterpret_cast<const float4*>(&g_va[0][1][lane * 4]);
    float4 vd0 = *reinterpret_cast<const float4*>(&g_va[0][2][lane * 4]);
    float4 vd1 = *reinterpret_cast<const float4*>(&g_va[0][3][lane * 4]);
    float ds0 = wred(n0 * vs0.x + n1 * vs0.y + n2 * vs0.z + n3 * vs0.w);
    float ds1 = wred(n0 * vs1.x + n1 * vs1.y + n2 * vs1.z + n3 * vs1.w);
    float dd0 = wred(n0 * vd0.x + n1 * vd0.y + n2 * vd0.z + n3 * vd0.w);
    float dd1 = wred(n0 * vd1.x + n1 * vd1.y + n2 * vd1.z + n3 * vd1.w);
    if (lane == 0) {
        *reinterpret_cast<float2*>(&g_as[row * 2]) = make_float2(ds0, ds1);
        *reinterpret_cast<float2*>(&g_ad[row * 2]) = make_float2(dd0, dd1);
    }
}

// ---------------- fp16 ldmatrix + mma GEMM, chunked rows ----------------
#define GEMM_SMEM 65536

__device__ __forceinline__ void ldm_x4(uint32_t* r, uint32_t addr) {
    asm volatile("ldmatrix.sync.aligned.m8n8.x4.shared.b16 {%0,%1,%2,%3}, [%4];"
                 : "=r"(r[0]), "=r"(r[1]), "=r"(r[2]), "=r"(r[3]) : "r"(addr));
}
__device__ __forceinline__ void mma_f16(float* c, const uint32_t* a,
                                        uint32_t b0, uint32_t b1) {
    asm volatile(
        "mma.sync.aligned.m16n8k16.row.col.f32.f16.f16.f32 "
        "{%0,%1,%2,%3}, {%4,%5,%6,%7}, {%8,%9}, {%0,%1,%2,%3};"
        : "+f"(c[0]), "+f"(c[1]), "+f"(c[2]), "+f"(c[3])
        : "r"(a[0]), "r"(a[1]), "r"(a[2]), "r"(a[3]), "r"(b0), "r"(b1));
}

__global__ __launch_bounds__(256, 2) void k_gemm(const __half* __restrict__ Wt,
                                                 int row_off, int row_end, int hbuf) {
    extern __shared__ uint4 smu[];
    int tid = threadIdx.x;
    int row0 = row_off + blockIdx.x * 128;
    int head = blockIdx.y;

#pragma unroll
    for (int i = 0; i < 8; i++) {
        int idx = i * 256 + tid;
        int r = idx >> 4, kb = idx & 15;
        int gr = row0 + r; if (gr >= row_end) gr = row_end - 1;
        uint4 v = *reinterpret_cast<const uint4*>(&g_xn[gr * 128 + kb * 8]);
        smu[r * 16 + (kb ^ (r & 7))] = v;
    }
#pragma unroll
    for (int i = 0; i < 8; i++) {
        int idx = i * 256 + tid;
        int nn = idx >> 4, kb = idx & 15;
        uint4 v = *reinterpret_cast<const uint4*>(&Wt[(head * 128 + nn) * 128 + kb * 8]);
        smu[2048 + nn * 16 + (kb ^ (nn & 7))] = v;
    }
    __syncthreads();

    uint32_t sA = (uint32_t)__cvta_generic_to_shared(smu);
    uint32_t sB = sA + 32768;

    int lane = tid & 31;
    int g = lane >> 2, t = lane & 3;
    int wid = tid >> 5;
    int arow = (wid & 3) * 32;
    int bcol = (wid >> 2) * 64;

    int a_mloc = ((lane >> 3) & 1) * 8 + (lane & 7);
    int a_kb   = lane >> 4;
    int b_nloc = ((lane >> 4) & 1) * 8 + (lane & 7);
    int b_kb   = (lane >> 3) & 1;

    float acc[2][8][4];
#pragma unroll
    for (int mt = 0; mt < 2; mt++)
#pragma unroll
        for (int nt = 0; nt < 8; nt++)
#pragma unroll
            for (int r = 0; r < 4; r++) acc[mt][nt][r] = 0.f;

#pragma unroll
    for (int kt = 0; kt < 8; kt++) {
        uint32_t a[2][4], bfr[4][4];
#pragma unroll
        for (int mt = 0; mt < 2; mt++) {
            int m = arow + mt * 16 + a_mloc;
            uint32_t addr = sA + (uint32_t)(m * 16 + ((kt * 2 + a_kb) ^ (m & 7))) * 16;
            ldm_x4(a[mt], addr);
        }
#pragma unroll
        for (int bj = 0; bj < 4; bj++) {
            int nn = bcol + bj * 16 + b_nloc;
            uint32_t addr = sB + (uint32_t)(nn * 16 + ((kt * 2 + b_kb) ^ (nn & 7))) * 16;
            ldm_x4(bfr[bj], addr);
        }
#pragma unroll
        for (int mt = 0; mt < 2; mt++)
#pragma unroll
            for (int bj = 0; bj < 4; bj++) {
                mma_f16(acc[mt][bj * 2],     a[mt], bfr[bj][0], bfr[bj][1]);
                mma_f16(acc[mt][bj * 2 + 1], a[mt], bfr[bj][2], bfr[bj][3]);
            }
    }

    // epilogue: stage bf16 tile in smem (stride 68 words), coalesced STG
    __syncthreads();
    uint32_t* sh = reinterpret_cast<uint32_t*>(smu);
#pragma unroll
    for (int mt = 0; mt < 2; mt++) {
        int r0 = arow + mt * 16 + g;
#pragma unroll
        for (int nt = 0; nt < 8; nt++) {
            int c32 = (bcol >> 1) + nt * 4 + t;
            __nv_bfloat162 p01 = __float22bfloat162_rn(
                make_float2(acc[mt][nt][0], acc[mt][nt][1]));
            __nv_bfloat162 p23 = __float22bfloat162_rn(
                make_float2(acc[mt][nt][2], acc[mt][nt][3]));
            sh[r0 * 68 + c32]       = *reinterpret_cast<uint32_t*>(&p01);
            sh[(r0 + 8) * 68 + c32] = *reinterpret_cast<uint32_t*>(&p23);
        }
    }
    __syncthreads();
    uint32_t* plane = g_h + (hbuf * 2 + head) * NN * 64;
#pragma unroll
    for (int i = 0; i < 16; i++) {
        int idx = i * 512 + tid * 2;
        int r = idx >> 6, c32 = idx & 63;
        int gr = row0 + r;
        if (gr < row_end) {
            uint2 val = *reinterpret_cast<uint2*>(&sh[r * 68 + c32]);
            *reinterpret_cast<uint2*>(&plane[gr * 64 + c32]) = val;
        }
    }
}

// ---------------- edge-parallel weight precompute ----------------
__global__ void k_ew(int tot) {
    int e = blockIdx.x * blockDim.x + threadIdx.x;
    if (e >= tot) return;
    int s = g_col[e], d = g_dst[e];
    float2 as = *reinterpret_cast<const float2*>(&g_as[s * 2]);
    float2 ad = *reinterpret_cast<const float2*>(&g_ad[d * 2]);
    float e0 = as.x + ad.x; e0 = e0 > 0.f ? e0 : 0.2f * e0;
    float e1 = as.y + ad.y; e1 = e1 > 0.f ? e1 : 0.2f * e1;
    g_w[e] = make_float2(__expf(e0), __expf(e1));
}

// ------- chunked aggregation + next-block LN/alphas -------
__global__ void k_agg(const float* __restrict__ bias, const float* __restrict__ resid,
                      float* __restrict__ out, int node_off, int node_cnt,
                      const float* __restrict__ gn, const float* __restrict__ bn,
                      int nb, int do_ln, int hbuf) {
    int node = node_off + blockIdx.x * 8 + (threadIdx.x >> 5);
    if (node >= node_off + node_cnt) return;
    int lane = threadIdx.x & 31;
    int s = g_rowptr[node], t = g_rowptr[node + 1];

    const uint32_t* plane0 = g_h + (hbuf * 2 + 0) * NN * 64;
    const uint32_t* plane1 = g_h + (hbuf * 2 + 1) * NN * 64;

    float4 a0 = make_float4(0.f, 0.f, 0.f, 0.f), a1 = a0;
    float s0 = 0.f, s1 = 0.f;

    for (int eb = s; eb < t; eb += 4) {
        int c[4];
        float w0[4], w1[4];
        c[0] = g_col[eb];
        float2 wv = g_w[eb];
        w0[0] = wv.x; w1[0] = wv.y;
#pragma unroll
        for (int j = 1; j < 4; j++) {
            if (eb + j < t) {
                c[j] = g_col[eb + j];
                float2 w = g_w[eb + j];
                w0[j] = w.x; w1[j] = w.y;
            } else {
                c[j] = c[0]; w0[j] = 0.f; w1[j] = 0.f;
            }
        }
#pragma unroll
        for (int j = 0; j < 4; j++) {
            uint2 u0 = *reinterpret_cast<const uint2*>(&plane0[c[j] * 64 + lane * 2]);
            uint2 u1 = *reinterpret_cast<const uint2*>(&plane1[c[j] * 64 + lane * 2]);
            float2 p0 = __bfloat1622float2(*reinterpret_cast<__nv_bfloat162*>(&u0.x));
            float2 p1 = __bfloat1622float2(*reinterpret_cast<__nv_bfloat162*>(&u0.y));
            float2 p2 = __bfloat1622float2(*reinterpret_cast<__nv_bfloat162*>(&u1.x));
            float2 p3 = __bfloat1622float2(*reinterpret_cast<__nv_bfloat162*>(&u1.y));
            a0.x += p0.x * w0[j]; a0.y += p0.y * w0[j];
            a0.z += p1.x * w0[j]; a0.w += p1.y * w0[j];
            a1.x += p2.x * w1[j]; a1.y += p2.y * w1[j];
            a1.z += p3.x * w1[j]; a1.w += p3.y * w1[j];
            s0 += w0[j]; s1 += w1[j];
        }
    }

    float i0 = 0.5f / (s0 + 1e-16f);
    float i1 = 0.5f / (s1 + 1e-16f);
    float4 bb = *reinterpret_cast<const float4*>(&bias[lane * 4]);
    float4 rr = *reinterpret_cast<const float4*>(&resid[node * DD + lane * 4]);
    float4 o4;
    o4.x = a0.x * i0 + a1.x * i1 + bb.x + rr.x;
    o4.y = a0.y * i0 + a1.y * i1 + bb.y + rr.y;
    o4.z = a0.z * i0 + a1.z * i1 + bb.z + rr.z;
    o4.w = a0.w * i0 + a1.w * i1 + bb.w + rr.w;
    *reinterpret_cast<float4*>(&out[node * DD + lane * 4]) = o4;

    if (do_ln) {
        float ss = wred(o4.x + o4.y + o4.z + o4.w);
        float qq = wred(o4.x * o4.x + o4.y * o4.y + o4.z * o4.z + o4.w * o4.w);
        float mu  = ss * (1.0f / DD);
        float var = qq * (1.0f / DD) - mu * mu;
        float rs  = rsqrtf(var + 1e-5f);
        float4 g4 = *reinterpret_cast<const float4*>(&gn[lane * 4]);
        float4 b4 = *reinterpret_cast<const float4*>(&bn[lane * 4]);
        float n0 = fmaxf(0.f, (o4.x - mu) * rs * g4.x + b4.x);
        float n1 = fmaxf(0.f, (o4.y - mu) * rs * g4.y + b4.y);
        float n2 = fmaxf(0.f, (o4.z - mu) * rs * g4.z + b4.z);
        float n3 = fmaxf(0.f, (o4.w - mu) * rs * g4.w + b4.w);
        __half2 h0 = __floats2half2_rn(n0, n1);
        __half2 h1 = __floats2half2_rn(n2, n3);
        uint2 u;
        u.x = *reinterpret_cast<uint32_t*>(&h0);
        u.y = *reinterpret_cast<uint32_t*>(&h1);
        *reinterpret_cast<uint2*>(&g_xn[node * DD + lane * 4]) = u;
        float4 vs0 = *reinterpret_cast<const float4*>(&g_va[nb][0][lane * 4]);
        float4 vs1 = *reinterpret_cast<const float4*>(&g_va[nb][1][lane * 4]);
        float4 vd0 = *reinterpret_cast<const float4*>(&g_va[nb][2][lane * 4]);
        float4 vd1 = *reinterpret_cast<const float4*>(&g_va[nb][3][lane * 4]);
        float ds0 = wred(n0 * vs0.x + n1 * vs0.y + n2 * vs0.z + n3 * vs0.w);
        float ds1 = wred(n0 * vs1.x + n1 * vs1.y + n2 * vs1.z + n3 * vs1.w);
        float dd0 = wred(n0 * vd0.x + n1 * vd0.y + n2 * vd0.z + n3 * vd0.w);
        float dd1 = wred(n0 * vd1.x + n1 * vd1.y + n2 * vd1.z + n3 * vd1.w);
        if (lane == 0) {
            *reinterpret_cast<float2*>(&g_as[node * 2]) = make_float2(ds0, ds1);
            *reinterpret_cast<float2*>(&g_ad[node * 2]) = make_float2(dd0, dd1);
        }
    }
}

// ---------------- launch ----------------
extern "C" void kernel_launch(void* const* d_in, const int* in_sizes, int n_in,
                              void* d_out, int out_size) {
    const float* x       = (const float*)d_in[0];
    const int*   ei      = (const int*)d_in[1];
    const float* W       = (const float*)d_in[2];
    const float* att_src = (const float*)d_in[3];
    const float* att_dst = (const float*)d_in[4];
    const float* bias    = (const float*)d_in[5];
    const float* gamma   = (const float*)d_in[6];
    const float* beta    = (const float*)d_in[7];
    float* out = (float*)d_out;

    int Nn  = in_sizes[0] / DD;
    int E   = in_sizes[1] / 2;
    int tot = E + Nn;

    // chunk split at tile granularity
    int C0 = ((Nn / 2 + 127) / 128) * 128;        // 25088
    if (C0 > Nn) C0 = Nn;
    int C1 = Nn - C0;
    int t0 = C0 / 128;                            // tiles in chunk0 (exact)
    int t1 = (C1 + 127) / 128;
    int a0b = (C0 + 7) / 8, a1b = (C1 + 7) / 8;

    cudaFuncSetAttribute(k_gemm, cudaFuncAttributeMaxDynamicSharedMemorySize, GEMM_SMEM);

    __half* wt_dev = nullptr;
    cudaGetSymbolAddress((void**)&wt_dev, g_Wt);

    cudaStream_t s2, s3;
    cudaStreamCreateWithFlags(&s2, cudaStreamNonBlocking);
    cudaStreamCreateWithFlags(&s3, cudaStreamNonBlocking);
    cudaEvent_t evF, evV, evW, evC, evL, evE[3], evG[2], evA[2][2];
    cudaEventCreateWithFlags(&evF, cudaEventDisableTiming);
    cudaEventCreateWithFlags(&evV, cudaEventDisableTiming);
    cudaEventCreateWithFlags(&evW, cudaEventDisableTiming);
    cudaEventCreateWithFlags(&evC, cudaEventDisableTiming);
    cudaEventCreateWithFlags(&evL, cudaEventDisableTiming);
    for (int i = 0; i < 3; i++) cudaEventCreateWithFlags(&evE[i], cudaEventDisableTiming);
    for (int i = 0; i < 2; i++) {
        cudaEventCreateWithFlags(&evG[i], cudaEventDisableTiming);
        cudaEventCreateWithFlags(&evA[i][0], cudaEventDisableTiming);
        cudaEventCreateWithFlags(&evA[i][1], cudaEventDisableTiming);
    }

    cudaEventRecord(evF, 0);
    cudaStreamWaitEvent(s2, evF, 0);
    cudaStreamWaitEvent(s3, evF, 0);

    // s2: va -> wt -> CSR
    k_va<<<3, 512, 0, s2>>>(W, att_src, att_dst);
    cudaEventRecord(evV, s2);
    k_wt<<<96, 256, 0, s2>>>(W);
    cudaEventRecord(evW, s2);
    k_count<<<(E + 255) / 256, 256, 0, s2>>>(ei, E);
    k_scan1<<<(Nn + 1023) / 1024, 1024, 0, s2>>>(Nn);
    k_scan3<<<(Nn + 255) / 256, 256, 0, s2>>>(Nn, tot);
    k_scatter<<<(tot + 255) / 256, 256, 0, s2>>>(ei, E, Nn);
    cudaEventRecord(evC, s2);

    // main: ln -> gemm0 (full, buf 0)
    cudaStreamWaitEvent(0, evV, 0);
    k_ln<<<(Nn + 7) / 8, 256>>>(x, gamma, beta, Nn);
    cudaEventRecord(evL, 0);
    cudaStreamWaitEvent(0, evW, 0);
    dim3 ggF((Nn + 127) / 128, 2);
    k_gemm<<<ggF, 256, GEMM_SMEM>>>(wt_dev, 0, Nn, 0);

    // s3: ew0 (needs CSR + alphas from ln), overlaps gemm0
    cudaStreamWaitEvent(s3, evC, 0);
    cudaStreamWaitEvent(s3, evL, 0);
    k_ew<<<(tot + 255) / 256, 256, 0, s3>>>(tot);
    cudaEventRecord(evE[0], s3);

    dim3 gg0(t0, 2), gg1(t1, 2);

    // ---- block 0: agg chunks (reads buf0), pipelined gemm1 (buf1) ----
    cudaStreamWaitEvent(0, evE[0], 0);
    k_agg<<<a0b, 256>>>(bias, x, out, 0, C0, gamma + DD, beta + DD, 1, 1, 0);
    cudaEventRecord(evA[0][0], 0);
    k_agg<<<a1b, 256>>>(bias, x, out, C0, C1, gamma + DD, beta + DD, 1, 1, 0);
    cudaEventRecord(evA[0][1], 0);

    cudaStreamWaitEvent(s2, evA[0][0], 0);
    k_gemm<<<gg0, 256, GEMM_SMEM, s2>>>(wt_dev + 32768, 0, C0, 1);
    cudaStreamWaitEvent(s2, evA[0][1], 0);
    k_gemm<<<gg1, 256, GEMM_SMEM, s2>>>(wt_dev + 32768, C0, Nn, 1);
    cudaEventRecord(evG[0], s2);

    cudaStreamWaitEvent(s3, evA[0][1], 0);
    k_ew<<<(tot + 255) / 256, 256, 0, s3>>>(tot);
    cudaEventRecord(evE[1], s3);

    // ---- block 1: agg chunks (reads buf1), pipelined gemm2 (buf0) ----
    cudaStreamWaitEvent(0, evG[0], 0);
    cudaStreamWaitEvent(0, evE[1], 0);
    k_agg<<<a0b, 256>>>(bias + CC, out, out, 0, C0, gamma + 2 * DD, beta + 2 * DD, 2, 1, 1);
    cudaEventRecord(evA[1][0], 0);
    k_agg<<<a1b, 256>>>(bias + CC, out, out, C0, C1, gamma + 2 * DD, beta + 2 * DD, 2, 1, 1);
    cudaEventRecord(evA[1][1], 0);

    cudaStreamWaitEvent(s2, evA[1][0], 0);
    k_gemm<<<gg0, 256, GEMM_SMEM, s2>>>(wt_dev + 2 * 32768, 0, C0, 0);
    cudaStreamWaitEvent(s2, evA[1][1], 0);
    k_gemm<<<gg1, 256, GEMM_SMEM, s2>>>(wt_dev + 2 * 32768, C0, Nn, 0);
    cudaEventRecord(evG[1], s2);

    cudaStreamWaitEvent(s3, evA[1][1], 0);
    k_ew<<<(tot + 255) / 256, 256, 0, s3>>>(tot);
    cudaEventRecord(evE[2], s3);

    // ---- block 2: full agg (reads buf0), no LN ----
    cudaStreamWaitEvent(0, evG[1], 0);
    cudaStreamWaitEvent(0, evE[2], 0);
    k_agg<<<(Nn + 7) / 8, 256>>>(bias + 2 * CC, out, out, 0, Nn, gamma, beta, 0, 0, 0);

    cudaEventDestroy(evF); cudaEventDestroy(evV); cudaEventDestroy(evW);
    cudaEventDestroy(evC); cudaEventDestroy(evL);
    for (int i = 0; i < 3; i++) cudaEventDestroy(evE[i]);
    for (int i = 0; i < 2; i++) {
        cudaEventDestroy(evG[i]);
        cudaEventDestroy(evA[i][0]);
        cudaEventDestroy(evA[i][1]);
    }
    cudaStreamDestroy(s2);
    cudaStreamDestroy(s3);
}

// round 15
// speedup vs baseline: 1.0855x; 1.0855x over previous
#include <cuda_runtime.h>
#include <cuda_bf16.h>
#include <cuda_fp16.h>
#include <cstdint>

#define NN 50000
#define EE 400000
#define DD 128
#define HH 2
#define CC 128
#define TE (EE + NN)

// ---------------- static scratch ----------------
__device__ __half g_xn[NN * DD];                 // fp16 relu(layernorm(x))
__device__ __half g_Wt[3 * 256 * 128];           // W^T per block, [n][k] fp16
__device__ uint32_t g_h[2 * NN * 64];            // bf16x2 msgs: [head][node][64]
__device__ float  g_va[3][4][128];               // W^T @ att vectors (s0,s1,d0,d1)
__device__ float  g_as[NN * HH];                 // alpha_src
__device__ float  g_ad[NN * HH];                 // alpha_dst
__device__ float2 g_w[TE];                       // per-edge softmax weights
__device__ int    g_rowptr[NN + 1];
__device__ int    g_wptr[NN];
__device__ int    g_col[TE];
__device__ int    g_dst[TE];
__device__ int    g_cnt[NN];                     // zero-init; self-resets each launch
__device__ int    g_bsum[64];

__device__ __forceinline__ float wred(float v) {
#pragma unroll
    for (int o = 16; o > 0; o >>= 1) v += __shfl_xor_sync(0xffffffffu, v, o);
    return v;
}

// ---------------- CSR build (multi-block scan) ----------------
__global__ void k_count(const int* __restrict__ ei, int E) {
    int e = blockIdx.x * blockDim.x + threadIdx.x;
    if (e < E) atomicAdd(&g_cnt[ei[E + e]], 1);
}

__global__ void k_scan1(int n) {
    __shared__ int wsum[32];
    int i = blockIdx.x * 1024 + threadIdx.x;
    int v = (i < n) ? (g_cnt[i] + 1) : 0;        // +1 = self-loop
    if (i < n) g_cnt[i] = 0;                     // reset for next graph replay
    int lane = threadIdx.x & 31, w = threadIdx.x >> 5;
    int s = v;
#pragma unroll
    for (int o = 1; o < 32; o <<= 1) {
        int t = __shfl_up_sync(0xffffffffu, s, o);
        if (lane >= o) s += t;
    }
    if (lane == 31) wsum[w] = s;
    __syncthreads();
    if (w == 0) {
        int t = wsum[lane];
#pragma unroll
        for (int o = 1; o < 32; o <<= 1) {
            int u = __shfl_up_sync(0xffffffffu, t, o);
            if (lane >= o) t += u;
        }
        wsum[lane] = t;
    }
    __syncthreads();
    int off  = (w > 0) ? wsum[w - 1] : 0;
    int incl = s + off;
    if (i < n) g_rowptr[i] = incl - v;
    if (threadIdx.x == 1023) g_bsum[blockIdx.x] = incl;
}

__global__ void k_scan3(int n, int tot) {
    __shared__ int pfx[2];
    int base = blockIdx.x * 256;
    if (threadIdx.x < 2) {
        int idx = base + (int)threadIdx.x * 255;
        if (idx >= n) idx = n - 1;
        int chunk = idx >> 10;
        int acc = 0;
        for (int j = 0; j < chunk; j++) acc += g_bsum[j];
        pfx[threadIdx.x] = acc;
    }
    __syncthreads();
    int i = base + threadIdx.x;
    if (i < n) {
        int sel = ((i >> 10) != (base >> 10)) ? 1 : 0;
        int r = g_rowptr[i] + pfx[sel];
        g_rowptr[i] = r;
        g_wptr[i]   = r;
    }
    if (i == 0) g_rowptr[n] = tot;
}

__global__ void k_scatter(const int* __restrict__ ei, int E, int n) {
    int e = blockIdx.x * blockDim.x + threadIdx.x;
    int tot = E + n;
    if (e >= tot) return;
    int s, d;
    if (e < E) { s = ei[e]; d = ei[E + e]; }
    else       { s = e - E; d = s; }
    int p = atomicAdd(&g_wptr[d], 1);
    g_col[p] = s;
    g_dst[p] = d;
}

// ---------------- va = W^T @ att vectors ----------------
__global__ void k_va(const float* __restrict__ W, const float* __restrict__ as_,
                     const float* __restrict__ ad_) {
    int b = blockIdx.x;
    int vec = threadIdx.x >> 7;
    int k   = threadIdx.x & 127;
    int h   = vec & 1;
    const float* av = (vec < 2 ? as_ : ad_) + b * 256 + h * 128;
    const float* wr = W + b * 32768 + k * 256 + h * 128;
    float sum = 0.f;
#pragma unroll 8
    for (int c = 0; c < 128; c++) sum += wr[c] * av[c];
    g_va[b][vec][k] = sum;
}

// ---------------- W transpose + fp16 convert ----------------
__global__ void k_wt(const float* __restrict__ W) {
    int idx = blockIdx.x * 256 + threadIdx.x;
    if (idx >= 3 * 128 * 64) return;
    int b  = idx >> 13;
    int r  = idx & 8191;
    int k  = r >> 6;
    int n4 = r & 63;
    float4 v = *reinterpret_cast<const float4*>(&W[b * 32768 + k * 256 + n4 * 4]);
    __half* dst = &g_Wt[b * 32768];
    dst[(n4 * 4 + 0) * 128 + k] = __float2half_rn(v.x);
    dst[(n4 * 4 + 1) * 128 + k] = __float2half_rn(v.y);
    dst[(n4 * 4 + 2) * 128 + k] = __float2half_rn(v.z);
    dst[(n4 * 4 + 3) * 128 + k] = __float2half_rn(v.w);
}

// ---------------- LayerNorm + ReLU -> fp16 + alphas (block 0) ----------------
__global__ void k_ln(const float* __restrict__ x, const float* __restrict__ gamma,
                     const float* __restrict__ beta, int n) {
    int row = blockIdx.x * 8 + (threadIdx.x >> 5);
    if (row >= n) return;
    int lane = threadIdx.x & 31;
    float4 v = *reinterpret_cast<const float4*>(&x[row * DD + lane * 4]);
    float s = wred(v.x + v.y + v.z + v.w);
    float q = wred(v.x * v.x + v.y * v.y + v.z * v.z + v.w * v.w);
    float mu  = s * (1.0f / DD);
    float var = q * (1.0f / DD) - mu * mu;
    float rs  = rsqrtf(var + 1e-5f);
    float4 g = *reinterpret_cast<const float4*>(&gamma[lane * 4]);
    float4 b = *reinterpret_cast<const float4*>(&beta[lane * 4]);
    float n0 = fmaxf(0.f, (v.x - mu) * rs * g.x + b.x);
    float n1 = fmaxf(0.f, (v.y - mu) * rs * g.y + b.y);
    float n2 = fmaxf(0.f, (v.z - mu) * rs * g.z + b.z);
    float n3 = fmaxf(0.f, (v.w - mu) * rs * g.w + b.w);
    __half2 h0 = __floats2half2_rn(n0, n1);
    __half2 h1 = __floats2half2_rn(n2, n3);
    uint2 u;
    u.x = *reinterpret_cast<uint32_t*>(&h0);
    u.y = *reinterpret_cast<uint32_t*>(&h1);
    *reinterpret_cast<uint2*>(&g_xn[row * DD + lane * 4]) = u;
    float4 vs0 = *reinterpret_cast<const float4*>(&g_va[0][0][lane * 4]);
    float4 vs1 = *reinterpret_cast<const float4*>(&g_va[0][1][lane * 4]);
    float4 vd0 = *reinterpret_cast<const float4*>(&g_va[0][2][lane * 4]);
    float4 vd1 = *reinterpret_cast<const float4*>(&g_va[0][3][lane * 4]);
    float ds0 = wred(n0 * vs0.x + n1 * vs0.y + n2 * vs0.z + n3 * vs0.w);
    float ds1 = wred(n0 * vs1.x + n1 * vs1.y + n2 * vs1.z + n3 * vs1.w);
    float dd0 = wred(n0 * vd0.x + n1 * vd0.y + n2 * vd0.z + n3 * vd0.w);
    float dd1 = wred(n0 * vd1.x + n1 * vd1.y + n2 * vd1.z + n3 * vd1.w);
    if (lane == 0) {
        *reinterpret_cast<float2*>(&g_as[row * 2]) = make_float2(ds0, ds1);
        *reinterpret_cast<float2*>(&g_ad[row * 2]) = make_float2(dd0, dd1);
    }
}

// ---------------- fp16 ldmatrix + mma GEMM, 128x128x128 tile ----------------
#define GEMM_SMEM 65536

__device__ __forceinline__ void ldm_x4(uint32_t* r, uint32_t addr) {
    asm volatile("ldmatrix.sync.aligned.m8n8.x4.shared.b16 {%0,%1,%2,%3}, [%4];"
                 : "=r"(r[0]), "=r"(r[1]), "=r"(r[2]), "=r"(r[3]) : "r"(addr));
}
__device__ __forceinline__ void mma_f16(float* c, const uint32_t* a,
                                        uint32_t b0, uint32_t b1) {
    asm volatile(
        "mma.sync.aligned.m16n8k16.row.col.f32.f16.f16.f32 "
        "{%0,%1,%2,%3}, {%4,%5,%6,%7}, {%8,%9}, {%0,%1,%2,%3};"
        : "+f"(c[0]), "+f"(c[1]), "+f"(c[2]), "+f"(c[3])
        : "r"(a[0]), "r"(a[1]), "r"(a[2]), "r"(a[3]), "r"(b0), "r"(b1));
}

__global__ __launch_bounds__(256, 2) void k_gemm(const __half* __restrict__ Wt, int M) {
    extern __shared__ uint4 smu[];
    int tid = threadIdx.x;
    int row0 = blockIdx.x * 128;
    int head = blockIdx.y;

#pragma unroll
    for (int i = 0; i < 8; i++) {
        int idx = i * 256 + tid;
        int r = idx >> 4, kb = idx & 15;
        int gr = row0 + r; if (gr >= M) gr = M - 1;
        uint4 v = *reinterpret_cast<const uint4*>(&g_xn[gr * 128 + kb * 8]);
        smu[r * 16 + (kb ^ (r & 7))] = v;
    }
#pragma unroll
    for (int i = 0; i < 8; i++) {
        int idx = i * 256 + tid;
        int nn = idx >> 4, kb = idx & 15;
        uint4 v = *reinterpret_cast<const uint4*>(&Wt[(head * 128 + nn) * 128 + kb * 8]);
        smu[2048 + nn * 16 + (kb ^ (nn & 7))] = v;
    }
    __syncthreads();

    uint32_t sA = (uint32_t)__cvta_generic_to_shared(smu);
    uint32_t sB = sA + 32768;

    int lane = tid & 31;
    int g = lane >> 2, t = lane & 3;
    int wid = tid >> 5;
    int arow = (wid & 3) * 32;
    int bcol = (wid >> 2) * 64;

    int a_mloc = ((lane >> 3) & 1) * 8 + (lane & 7);
    int a_kb   = lane >> 4;
    int b_nloc = ((lane >> 4) & 1) * 8 + (lane & 7);
    int b_kb   = (lane >> 3) & 1;

    float acc[2][8][4];
#pragma unroll
    for (int mt = 0; mt < 2; mt++)
#pragma unroll
        for (int nt = 0; nt < 8; nt++)
#pragma unroll
            for (int r = 0; r < 4; r++) acc[mt][nt][r] = 0.f;

#pragma unroll
    for (int kt = 0; kt < 8; kt++) {
        uint32_t a[2][4], bfr[4][4];
#pragma unroll
        for (int mt = 0; mt < 2; mt++) {
            int m = arow + mt * 16 + a_mloc;
            uint32_t addr = sA + (uint32_t)(m * 16 + ((kt * 2 + a_kb) ^ (m & 7))) * 16;
            ldm_x4(a[mt], addr);
        }
#pragma unroll
        for (int bj = 0; bj < 4; bj++) {
            int nn = bcol + bj * 16 + b_nloc;
            uint32_t addr = sB + (uint32_t)(nn * 16 + ((kt * 2 + b_kb) ^ (nn & 7))) * 16;
            ldm_x4(bfr[bj], addr);
        }
#pragma unroll
        for (int mt = 0; mt < 2; mt++)
#pragma unroll
            for (int bj = 0; bj < 4; bj++) {
                mma_f16(acc[mt][bj * 2],     a[mt], bfr[bj][0], bfr[bj][1]);
                mma_f16(acc[mt][bj * 2 + 1], a[mt], bfr[bj][2], bfr[bj][3]);
            }
    }

    // epilogue: stage bf16 tile in smem (stride 68 words), coalesced STG
    __syncthreads();
    uint32_t* sh = reinterpret_cast<uint32_t*>(smu);
#pragma unroll
    for (int mt = 0; mt < 2; mt++) {
        int r0 = arow + mt * 16 + g;
#pragma unroll
        for (int nt = 0; nt < 8; nt++) {
            int c32 = (bcol >> 1) + nt * 4 + t;
            __nv_bfloat162 p01 = __float22bfloat162_rn(
                make_float2(acc[mt][nt][0], acc[mt][nt][1]));
            __nv_bfloat162 p23 = __float22bfloat162_rn(
                make_float2(acc[mt][nt][2], acc[mt][nt][3]));
            sh[r0 * 68 + c32]       = *reinterpret_cast<uint32_t*>(&p01);
            sh[(r0 + 8) * 68 + c32] = *reinterpret_cast<uint32_t*>(&p23);
        }
    }
    __syncthreads();
    uint32_t* plane = g_h + head * NN * 64;
#pragma unroll
    for (int i = 0; i < 16; i++) {
        int idx = i * 512 + tid * 2;
        int r = idx >> 6, c32 = idx & 63;
        int gr = row0 + r;
        if (gr < M) {
            uint2 val = *reinterpret_cast<uint2*>(&sh[r * 68 + c32]);
            *reinterpret_cast<uint2*>(&plane[gr * 64 + c32]) = val;
        }
    }
}

// ---------------- edge-parallel weight precompute ----------------
__global__ void k_ew(int tot) {
    int e = blockIdx.x * blockDim.x + threadIdx.x;
    if (e >= tot) return;
    int s = g_col[e], d = g_dst[e];
    float2 as = *reinterpret_cast<const float2*>(&g_as[s * 2]);
    float2 ad = *reinterpret_cast<const float2*>(&g_ad[d * 2]);
    float e0 = as.x + ad.x; e0 = e0 > 0.f ? e0 : 0.2f * e0;
    float e1 = as.y + ad.y; e1 = e1 > 0.f ? e1 : 0.2f * e1;
    g_w[e] = make_float2(__expf(e0), __expf(e1));
}

// ------- aggregation + next-block LN/alphas -------
__global__ void k_agg(const float* __restrict__ bias, const float* __restrict__ resid,
                      float* __restrict__ out, int n,
                      const float* __restrict__ gn, const float* __restrict__ bn,
                      int nb, int do_ln) {
    int node = blockIdx.x * 8 + (threadIdx.x >> 5);
    if (node >= n) return;
    int lane = threadIdx.x & 31;
    int s = g_rowptr[node], t = g_rowptr[node + 1];

    const uint32_t* plane0 = g_h;
    const uint32_t* plane1 = g_h + NN * 64;

    float4 a0 = make_float4(0.f, 0.f, 0.f, 0.f), a1 = a0;
    float s0 = 0.f, s1 = 0.f;

    for (int eb = s; eb < t; eb += 4) {
        int c[4];
        float w0[4], w1[4];
        c[0] = g_col[eb];
        float2 wv = g_w[eb];
        w0[0] = wv.x; w1[0] = wv.y;
#pragma unroll
        for (int j = 1; j < 4; j++) {
            if (eb + j < t) {
                c[j] = g_col[eb + j];
                float2 w = g_w[eb + j];
                w0[j] = w.x; w1[j] = w.y;
            } else {
                c[j] = c[0]; w0[j] = 0.f; w1[j] = 0.f;
            }
        }
#pragma unroll
        for (int j = 0; j < 4; j++) {
            uint2 u0 = *reinterpret_cast<const uint2*>(&plane0[c[j] * 64 + lane * 2]);
            uint2 u1 = *reinterpret_cast<const uint2*>(&plane1[c[j] * 64 + lane * 2]);
            float2 p0 = __bfloat1622float2(*reinterpret_cast<__nv_bfloat162*>(&u0.x));
            float2 p1 = __bfloat1622float2(*reinterpret_cast<__nv_bfloat162*>(&u0.y));
            float2 p2 = __bfloat1622float2(*reinterpret_cast<__nv_bfloat162*>(&u1.x));
            float2 p3 = __bfloat1622float2(*reinterpret_cast<__nv_bfloat162*>(&u1.y));
            a0.x += p0.x * w0[j]; a0.y += p0.y * w0[j];
            a0.z += p1.x * w0[j]; a0.w += p1.y * w0[j];
            a1.x += p2.x * w1[j]; a1.y += p2.y * w1[j];
            a1.z += p3.x * w1[j]; a1.w += p3.y * w1[j];
            s0 += w0[j]; s1 += w1[j];
        }
    }

    float i0 = 0.5f / (s0 + 1e-16f);
    float i1 = 0.5f / (s1 + 1e-16f);
    float4 bb = *reinterpret_cast<const float4*>(&bias[lane * 4]);
    float4 rr = *reinterpret_cast<const float4*>(&resid[node * DD + lane * 4]);
    float4 o4;
    o4.x = a0.x * i0 + a1.x * i1 + bb.x + rr.x;
    o4.y = a0.y * i0 + a1.y * i1 + bb.y + rr.y;
    o4.z = a0.z * i0 + a1.z * i1 + bb.z + rr.z;
    o4.w = a0.w * i0 + a1.w * i1 + bb.w + rr.w;
    *reinterpret_cast<float4*>(&out[node * DD + lane * 4]) = o4;

    if (do_ln) {
        float ss = wred(o4.x + o4.y + o4.z + o4.w);
        float qq = wred(o4.x * o4.x + o4.y * o4.y + o4.z * o4.z + o4.w * o4.w);
        float mu  = ss * (1.0f / DD);
        float var = qq * (1.0f / DD) - mu * mu;
        float rs  = rsqrtf(var + 1e-5f);
        float4 g4 = *reinterpret_cast<const float4*>(&gn[lane * 4]);
        float4 b4 = *reinterpret_cast<const float4*>(&bn[lane * 4]);
        float n0 = fmaxf(0.f, (o4.x - mu) * rs * g4.x + b4.x);
        float n1 = fmaxf(0.f, (o4.y - mu) * rs * g4.y + b4.y);
        float n2 = fmaxf(0.f, (o4.z - mu) * rs * g4.z + b4.z);
        float n3 = fmaxf(0.f, (o4.w - mu) * rs * g4.w + b4.w);
        __half2 h0 = __floats2half2_rn(n0, n1);
        __half2 h1 = __floats2half2_rn(n2, n3);
        uint2 u;
        u.x = *reinterpret_cast<uint32_t*>(&h0);
        u.y = *reinterpret_cast<uint32_t*>(&h1);
        *reinterpret_cast<uint2*>(&g_xn[node * DD + lane * 4]) = u;
        float4 vs0 = *reinterpret_cast<const float4*>(&g_va[nb][0][lane * 4]);
        float4 vs1 = *reinterpret_cast<const float4*>(&g_va[nb][1][lane * 4]);
        float4 vd0 = *reinterpret_cast<const float4*>(&g_va[nb][2][lane * 4]);
        float4 vd1 = *reinterpret_cast<const float4*>(&g_va[nb][3][lane * 4]);
        float ds0 = wred(n0 * vs0.x + n1 * vs0.y + n2 * vs0.z + n3 * vs0.w);
        float ds1 = wred(n0 * vs1.x + n1 * vs1.y + n2 * vs1.z + n3 * vs1.w);
        float dd0 = wred(n0 * vd0.x + n1 * vd0.y + n2 * vd0.z + n3 * vd0.w);
        float dd1 = wred(n0 * vd1.x + n1 * vd1.y + n2 * vd1.z + n3 * vd1.w);
        if (lane == 0) {
            *reinterpret_cast<float2*>(&g_as[node * 2]) = make_float2(ds0, ds1);
            *reinterpret_cast<float2*>(&g_ad[node * 2]) = make_float2(dd0, dd1);
        }
    }
}

// ---------------- launch ----------------
extern "C" void kernel_launch(void* const* d_in, const int* in_sizes, int n_in,
                              void* d_out, int out_size) {
    const float* x       = (const float*)d_in[0];
    const int*   ei      = (const int*)d_in[1];
    const float* W       = (const float*)d_in[2];
    const float* att_src = (const float*)d_in[3];
    const float* att_dst = (const float*)d_in[4];
    const float* bias    = (const float*)d_in[5];
    const float* gamma   = (const float*)d_in[6];
    const float* beta    = (const float*)d_in[7];
    float* out = (float*)d_out;

    int Nn  = in_sizes[0] / DD;
    int E   = in_sizes[1] / 2;
    int tot = E + Nn;

    cudaFuncSetAttribute(k_gemm, cudaFuncAttributeMaxDynamicSharedMemorySize, GEMM_SMEM);

    __half* wt_dev = nullptr;
    cudaGetSymbolAddress((void**)&wt_dev, g_Wt);

    cudaStream_t s2, s3;
    cudaStreamCreateWithFlags(&s2, cudaStreamNonBlocking);
    cudaStreamCreateWithFlags(&s3, cudaStreamNonBlocking);
    cudaEvent_t evF, evV, evW, evC, evL, evG0m, evE[3], evG[2], evA[2];
    cudaEventCreateWithFlags(&evF, cudaEventDisableTiming);
    cudaEventCreateWithFlags(&evV, cudaEventDisableTiming);
    cudaEventCreateWithFlags(&evW, cudaEventDisableTiming);
    cudaEventCreateWithFlags(&evC, cudaEventDisableTiming);
    cudaEventCreateWithFlags(&evL, cudaEventDisableTiming);
    cudaEventCreateWithFlags(&evG0m, cudaEventDisableTiming);
    for (int i = 0; i < 3; i++) cudaEventCreateWithFlags(&evE[i], cudaEventDisableTiming);
    for (int i = 0; i < 2; i++) {
        cudaEventCreateWithFlags(&evG[i], cudaEventDisableTiming);
        cudaEventCreateWithFlags(&evA[i], cudaEventDisableTiming);
    }

    cudaEventRecord(evF, 0);
    cudaStreamWaitEvent(s2, evF, 0);
    cudaStreamWaitEvent(s3, evF, 0);

    // s2: va -> wt -> CSR
    k_va<<<3, 512, 0, s2>>>(W, att_src, att_dst);
    cudaEventRecord(evV, s2);
    k_wt<<<96, 256, 0, s2>>>(W);
    cudaEventRecord(evW, s2);
    k_count<<<(E + 255) / 256, 256, 0, s2>>>(ei, E);
    k_scan1<<<(Nn + 1023) / 1024, 1024, 0, s2>>>(Nn);
    k_scan3<<<(Nn + 255) / 256, 256, 0, s2>>>(Nn, tot);
    k_scatter<<<(tot + 255) / 256, 256, 0, s2>>>(ei, E, Nn);
    cudaEventRecord(evC, s2);

    // main: ln -> gemm0
    cudaStreamWaitEvent(0, evV, 0);
    k_ln<<<(Nn + 7) / 8, 256>>>(x, gamma, beta, Nn);
    cudaEventRecord(evL, 0);
    cudaStreamWaitEvent(0, evW, 0);
    dim3 gg((Nn + 127) / 128, 2);
    k_gemm<<<gg, 256, GEMM_SMEM>>>(wt_dev, Nn);
    cudaEventRecord(evG0m, 0);   // gemm0 done (main stream)

    // s3: ew0 (CSR + alphas from ln), overlaps gemm0
    cudaStreamWaitEvent(s3, evC, 0);
    cudaStreamWaitEvent(s3, evL, 0);
    k_ew<<<(tot + 255) / 256, 256, 0, s3>>>(tot);
    cudaEventRecord(evE[0], s3);

    for (int b = 0; b < 3; b++) {
        const float* xc = (b == 0) ? x : (const float*)out;
        if (b > 0) cudaStreamWaitEvent(0, evG[b - 1], 0);   // gemm_b done (s2)
        cudaStreamWaitEvent(0, evE[b], 0);                  // ew_b done (s3)
        int do_ln = (b < 2) ? 1 : 0;
        int nb = (b + 1 < 3) ? (b + 1) : 0;
        const float* gn = gamma + nb * DD;
        const float* bn = beta  + nb * DD;
        k_agg<<<(Nn + 7) / 8, 256>>>(bias + b * CC, xc, out, Nn, gn, bn, nb, do_ln);
        if (b < 2) {
            cudaEventRecord(evA[b], 0);
            // gemm_{b+1} on s2, ew_{b+1} on s3 -- both depend only on agg_b
            cudaStreamWaitEvent(s2, evA[b], 0);
            k_gemm<<<gg, 256, GEMM_SMEM, s2>>>(wt_dev + (b + 1) * 32768, Nn);
            cudaEventRecord(evG[b], s2);
            cudaStreamWaitEvent(s3, evA[b], 0);
            k_ew<<<(tot + 255) / 256, 256, 0, s3>>>(tot);
            cudaEventRecord(evE[b + 1], s3);
        }
    }

    cudaEventDestroy(evF); cudaEventDestroy(evV); cudaEventDestroy(evW);
    cudaEventDestroy(evC); cudaEventDestroy(evL); cudaEventDestroy(evG0m);
    for (int i = 0; i < 3; i++) cudaEventDestroy(evE[i]);
    for (int i = 0; i < 2; i++) { cudaEventDestroy(evG[i]); cudaEventDestroy(evA[i]); }
    cudaStreamDestroy(s2);
    cudaStreamDestroy(s3);
}